// round 2
// baseline (speedup 1.0000x reference)
#include <cuda_runtime.h>

#define Bn 8192
#define Dd 256
#define MT 128
#define NT 64
#define KS 260           // padded smem row stride (floats): bank-conflict-free float4 reads
#define NSPLIT 8
#define CPB (Bn / NSPLIT)     // 1024 columns per block
#define NCHUNK (CPB / NT)     // 16 chunks

// ---- scratch (no allocation allowed) ----
__device__ float g_sq[Bn];
__device__ int g_lab[Bn];
__device__ unsigned long long g_pos[Bn];
__device__ unsigned long long g_neg[Bn];
__device__ float g_loss[Bn];
__device__ int g_valid[Bn];
__device__ int g_l64;   // 1 if labels buffer is int64-layout, 0 if int32

// ---------------- label dtype layout probe ----------------
// int64 labels in 0..7 => every odd 32-bit word is 0. For int32 labels the
// probability that 128 odd words are all zero is 8^-128 ~ 0.
__global__ void detect_kernel(const int* __restrict__ lab32) {
    int any = 0;
    for (int i = 1; i < 256; i += 2) any |= lab32[i];
    g_l64 = (any == 0) ? 1 : 0;
}

// ---------------- prep: norms, labels, sentinel init ----------------
__global__ void prep_kernel(const float* __restrict__ X, const int* __restrict__ lab32) {
    int row = blockIdx.x;
    int t = threadIdx.x;  // 64 threads
    const float4* x4 = (const float4*)(X + (size_t)row * Dd);
    float4 v = x4[t];
    float s = v.x * v.x + v.y * v.y + v.z * v.z + v.w * v.w;
#pragma unroll
    for (int o = 16; o > 0; o >>= 1) s += __shfl_xor_sync(0xffffffffu, s, o);
    __shared__ float ws[2];
    if ((t & 31) == 0) ws[t >> 5] = s;
    __syncthreads();
    if (t == 0) {
        g_sq[row] = ws[0] + ws[1];
        g_lab[row] = g_l64 ? lab32[2 * row] : lab32[row];
        g_pos[row] = 0ull;      // "no positive seen" sentinel
        g_neg[row] = ~0ull;     // "no negative seen" sentinel
    }
}

// ---------------- fused GEMM + hard mining ----------------
__global__ void __launch_bounds__(256, 1) mine_kernel(const float* __restrict__ X) {
    extern __shared__ float sm[];
    float* As = sm;                       // [MT][KS]
    float* Bs = sm + MT * KS;             // [NT][KS]
    float* sqS = Bs + NT * KS;            // [NT]
    int* lbS = (int*)(sqS + NT);          // [NT]

    int tid = threadIdx.x;
    int row0 = blockIdx.x * MT;
    int col0 = blockIdx.y * CPB;

    // Load anchor tile once (row-major, k-contiguous: coalesced, conflict-free)
    for (int i = tid; i < MT * (Dd / 4); i += 256) {
        int r = i >> 6, k4 = i & 63;
        float4 v = ((const float4*)(X + (size_t)(row0 + r) * Dd))[k4];
        *(float4*)(As + r * KS + 4 * k4) = v;
    }

    // Thread tile: 4 rows (tm + 32r) x 8 cols (tn + 8c)
    int tm = tid >> 3;  // 0..31
    int tn = tid & 7;   // 0..7

    int myrow[4];
    float mysq[4];
    int mylab[4];
#pragma unroll
    for (int r = 0; r < 4; r++) {
        myrow[r] = row0 + tm + 32 * r;
        mysq[r] = g_sq[myrow[r]];
        mylab[r] = g_lab[myrow[r]];
    }
    unsigned long long bP[4], bN[4];
#pragma unroll
    for (int r = 0; r < 4; r++) { bP[r] = 0ull; bN[r] = ~0ull; }

    __syncthreads();

    for (int ch = 0; ch < NCHUNK; ch++) {
        int cbase = col0 + ch * NT;
        // load 64-column tile (full K resident)
        for (int i = tid; i < NT * (Dd / 4); i += 256) {
            int r = i >> 6, k4 = i & 63;
            float4 v = ((const float4*)(X + (size_t)(cbase + r) * Dd))[k4];
            *(float4*)(Bs + r * KS + 4 * k4) = v;
        }
        if (tid < NT) {
            sqS[tid] = g_sq[cbase + tid];
            lbS[tid] = g_lab[cbase + tid];
        }
        __syncthreads();

        float acc[4][8];
#pragma unroll
        for (int r = 0; r < 4; r++)
#pragma unroll
            for (int c = 0; c < 8; c++) acc[r][c] = 0.f;

#pragma unroll 2
        for (int k4 = 0; k4 < Dd / 4; k4++) {
            float4 a[4], b[8];
#pragma unroll
            for (int r = 0; r < 4; r++)
                a[r] = *(const float4*)(As + (tm + 32 * r) * KS + 4 * k4);
#pragma unroll
            for (int c = 0; c < 8; c++)
                b[c] = *(const float4*)(Bs + (tn + 8 * c) * KS + 4 * k4);
#pragma unroll
            for (int r = 0; r < 4; r++)
#pragma unroll
                for (int c = 0; c < 8; c++) {
                    acc[r][c] += a[r].x * b[c].x;
                    acc[r][c] += a[r].y * b[c].y;
                    acc[r][c] += a[r].z * b[c].z;
                    acc[r][c] += a[r].w * b[c].w;
                }
        }

        // mining epilogue for this 128x64 tile
#pragma unroll
        for (int r = 0; r < 4; r++) {
#pragma unroll
            for (int c = 0; c < 8; c++) {
                int n = tn + 8 * c;
                int col = cbase + n;
                float d2 = fmaxf(mysq[r] + sqS[n] - 2.f * acc[r][c], 0.f);
                unsigned int db = __float_as_uint(d2);
                if (lbS[n] == mylab[r]) {
                    if (col != myrow[r]) {
                        unsigned long long pk =
                            ((unsigned long long)db << 32) | (unsigned int)(~(unsigned int)col);
                        if (pk > bP[r]) bP[r] = pk;  // max d2, ties -> lowest col
                    }
                } else {
                    unsigned long long pk =
                        ((unsigned long long)db << 32) | (unsigned int)col;
                    if (pk < bN[r]) bN[r] = pk;      // min d2, ties -> lowest col
                }
            }
        }
        __syncthreads();
    }

    // merge across the 8 lanes sharing each row, then global atomics
#pragma unroll
    for (int r = 0; r < 4; r++) {
#pragma unroll
        for (int o = 1; o < 8; o <<= 1) {
            unsigned long long p = __shfl_xor_sync(0xffffffffu, bP[r], o);
            if (p > bP[r]) bP[r] = p;
            unsigned long long q = __shfl_xor_sync(0xffffffffu, bN[r], o);
            if (q < bN[r]) bN[r] = q;
        }
        if (tn == 0) {
            atomicMax(&g_pos[myrow[r]], bP[r]);
            atomicMin(&g_neg[myrow[r]], bN[r]);
        }
    }
}

// ---------------- exact per-anchor recompute (F.pairwise_distance semantics) ----------------
__global__ void loss_kernel(const float* __restrict__ X) {
    int a = blockIdx.x;
    int t = threadIdx.x;  // 64 threads
    unsigned long long p = g_pos[a];
    unsigned long long q = g_neg[a];
    bool valid = (p != 0ull) && (q != ~0ull);
    float lp = 0.f, ln = 0.f;
    if (valid) {
        int pi = (int)(~(unsigned int)(p & 0xFFFFFFFFull));
        int ni = (int)(unsigned int)(q & 0xFFFFFFFFull);
        float4 va = ((const float4*)(X + (size_t)a * Dd))[t];
        float4 vp = ((const float4*)(X + (size_t)pi * Dd))[t];
        float4 vn = ((const float4*)(X + (size_t)ni * Dd))[t];
        float d;
        d = va.x - vp.x + 1e-6f; lp += d * d;
        d = va.y - vp.y + 1e-6f; lp += d * d;
        d = va.z - vp.z + 1e-6f; lp += d * d;
        d = va.w - vp.w + 1e-6f; lp += d * d;
        d = va.x - vn.x + 1e-6f; ln += d * d;
        d = va.y - vn.y + 1e-6f; ln += d * d;
        d = va.z - vn.z + 1e-6f; ln += d * d;
        d = va.w - vn.w + 1e-6f; ln += d * d;
    }
#pragma unroll
    for (int o = 16; o > 0; o >>= 1) {
        lp += __shfl_xor_sync(0xffffffffu, lp, o);
        ln += __shfl_xor_sync(0xffffffffu, ln, o);
    }
    __shared__ float s[4];
    if ((t & 31) == 0) { s[(t >> 5) * 2] = lp; s[(t >> 5) * 2 + 1] = ln; }
    __syncthreads();
    if (t == 0) {
        float pd = sqrtf(s[0] + s[2]);
        float nd = sqrtf(s[1] + s[3]);
        float v = pd - nd + 0.3f;
        g_loss[a] = valid ? (v > 0.f ? v : 0.f) : 0.f;
        g_valid[a] = valid ? 1 : 0;
    }
}

// ---------------- deterministic final reduction ----------------
__global__ void final_kernel(float* __restrict__ out) {
    int t = threadIdx.x;  // 1024
    float s = 0.f;
    int c = 0;
#pragma unroll
    for (int j = 0; j < Bn / 1024; j++) {
        s += g_loss[t + j * 1024];
        c += g_valid[t + j * 1024];
    }
    __shared__ float ss[1024];
    __shared__ int cc[1024];
    ss[t] = s;
    cc[t] = c;
    __syncthreads();
    for (int o = 512; o > 0; o >>= 1) {
        if (t < o) { ss[t] += ss[t + o]; cc[t] += cc[t + o]; }
        __syncthreads();
    }
    if (t == 0) out[0] = ss[0] / (float)(cc[0] > 0 ? cc[0] : 1);
}

extern "C" void kernel_launch(void* const* d_in, const int* in_sizes, int n_in,
                              void* d_out, int out_size) {
    const float* X = (const float*)d_in[0];
    const int* lab32 = (const int*)d_in[1];
    float* out = (float*)d_out;

    size_t smem = (size_t)(MT * KS + NT * KS + NT) * sizeof(float) + NT * sizeof(int);
    cudaFuncSetAttribute(mine_kernel, cudaFuncAttributeMaxDynamicSharedMemorySize, (int)smem);

    detect_kernel<<<1, 1>>>(lab32);
    prep_kernel<<<Bn, 64>>>(X, lab32);
    mine_kernel<<<dim3(Bn / MT, NSPLIT), 256, smem>>>(X);
    loss_kernel<<<Bn, 64>>>(X);
    final_kernel<<<1, 1024>>>(out);
}

// round 4
// speedup vs baseline: 5.2003x; 5.2003x over previous
#include <cuda_runtime.h>
#include <cuda_bf16.h>
#include <cstdint>

#define Bn 8192
#define Dd 256
#define MT 128                 // anchors per CTA
#define NTILE 128              // candidates per tile
#define NSPLIT 2
#define CPB (Bn / NSPLIT)      // 4096 cols per CTA
#define NTILES (CPB / NTILE)   // 32
#define ASTR 528               // smem row stride in bytes (264 bf16, pad 8)
#define BBYTES (128 * ASTR)    // 67584 per B buffer

// smem layout (bytes)
#define SM_SQLB 0              // 2 x 128 float2 = 2048
#define SM_A 2048              // 128 x 528 = 67584
#define SM_B 69632             // 2 x 67584 = 135168
#define SM_TOTAL 204800

// ---- scratch (no allocation allowed) ----
__device__ float2 g_sqlab[Bn];          // (sqnorm, label bits)
__device__ unsigned long long g_pos[Bn];
__device__ unsigned long long g_neg[Bn];
__device__ float g_loss[Bn];
__device__ int g_valid[Bn];
__device__ int g_l64;
__device__ __nv_bfloat16 g_Xh[(size_t)Bn * Dd];   // 4MB bf16 copy

// ---------------- helpers ----------------
__device__ __forceinline__ uint32_t smem_u32(const void* p) {
    uint32_t a;
    asm("{ .reg .u64 t; cvta.to.shared.u64 t, %1; cvt.u32.u64 %0, t; }" : "=r"(a) : "l"(p));
    return a;
}
__device__ __forceinline__ void ldm_x4(uint32_t& r0, uint32_t& r1, uint32_t& r2, uint32_t& r3,
                                       uint32_t addr) {
    asm volatile("ldmatrix.sync.aligned.m8n8.x4.shared.b16 {%0,%1,%2,%3}, [%4];"
                 : "=r"(r0), "=r"(r1), "=r"(r2), "=r"(r3) : "r"(addr));
}
__device__ __forceinline__ void mma16816(float* c, const uint32_t* a, const uint32_t* b) {
    asm volatile(
        "mma.sync.aligned.m16n8k16.row.col.f32.bf16.bf16.f32 "
        "{%0,%1,%2,%3}, {%4,%5,%6,%7}, {%8,%9}, {%0,%1,%2,%3};"
        : "+f"(c[0]), "+f"(c[1]), "+f"(c[2]), "+f"(c[3])
        : "r"(a[0]), "r"(a[1]), "r"(a[2]), "r"(a[3]), "r"(b[0]), "r"(b[1]));
}
__device__ __forceinline__ void cp16(uint32_t dst, const void* src) {
    asm volatile("cp.async.cg.shared.global [%0], [%1], 16;" :: "r"(dst), "l"(src) : "memory");
}
__device__ __forceinline__ void cp8(uint32_t dst, const void* src) {
    asm volatile("cp.async.ca.shared.global [%0], [%1], 8;" :: "r"(dst), "l"(src) : "memory");
}
__device__ __forceinline__ void cp_commit() { asm volatile("cp.async.commit_group;" ::: "memory"); }
__device__ __forceinline__ void cp_wait0() { asm volatile("cp.async.wait_group 0;" ::: "memory"); }

// ---------------- label dtype layout probe ----------------
__global__ void detect_kernel(const int* __restrict__ lab32) {
    int any = 0;
    for (int i = 1; i < 256; i += 2) any |= lab32[i];
    g_l64 = (any == 0) ? 1 : 0;
}

// ---------------- prep: norms, bf16 copy, labels, sentinels ----------------
__global__ void prep_kernel(const float* __restrict__ X, const int* __restrict__ lab32) {
    int row = blockIdx.x;
    int t = threadIdx.x;  // 64 threads
    const float4* x4 = (const float4*)(X + (size_t)row * Dd);
    float4 v = x4[t];
    __nv_bfloat162 p0 = __nv_bfloat162(__float2bfloat16(v.x), __float2bfloat16(v.y));
    __nv_bfloat162 p1 = __nv_bfloat162(__float2bfloat16(v.z), __float2bfloat16(v.w));
    uint2 pk;
    pk.x = *(uint32_t*)&p0;
    pk.y = *(uint32_t*)&p1;
    *(uint2*)(g_Xh + (size_t)row * Dd + 4 * t) = pk;

    float s = v.x * v.x + v.y * v.y + v.z * v.z + v.w * v.w;
#pragma unroll
    for (int o = 16; o > 0; o >>= 1) s += __shfl_xor_sync(0xffffffffu, s, o);
    __shared__ float ws[2];
    if ((t & 31) == 0) ws[t >> 5] = s;
    __syncthreads();
    if (t == 0) {
        float2 sl;
        sl.x = ws[0] + ws[1];
        sl.y = __int_as_float(g_l64 ? lab32[2 * row] : lab32[row]);
        g_sqlab[row] = sl;
        g_pos[row] = 0ull;
        g_neg[row] = ~0ull;
    }
}

// ---------------- HMMA fused GEMM + hard mining ----------------
__global__ void __launch_bounds__(256, 1) mine_tc(void) {
    extern __shared__ char sm[];
    uint32_t smb = smem_u32(sm);
    int tid = threadIdx.x;
    int wid = tid >> 5;
    int lane = tid & 31;

    int row0 = blockIdx.x * MT;
    int colbase = blockIdx.y * CPB;

    int warp_m = wid & 3;      // 4-way M split (32 rows each)
    int warp_n = wid >> 2;     // 2-way N split (64 cols each)
    int mrow0 = warp_m * 32;
    int ncol0 = warp_n * 64;

    // ldmatrix per-lane addressing pieces
    int lrow8 = (((lane >> 3) & 1) << 3) + (lane & 7);
    int lk8b = ((lane >> 4) & 1) * 16;   // byte offset for k half (8 bf16)

    uint32_t a_addr[2];
#pragma unroll
    for (int mf = 0; mf < 2; mf++)
        a_addr[mf] = smb + SM_A + (uint32_t)(mrow0 + mf * 16 + lrow8) * ASTR + lk8b;

    // row metadata (tile-invariant)
    float mysq[4];
    int mylab[4], myrowg[4];
#pragma unroll
    for (int mf = 0; mf < 2; mf++)
#pragma unroll
        for (int h = 0; h < 2; h++) {
            int rid = mf * 2 + h;
            int rg = row0 + mrow0 + mf * 16 + h * 8 + (lane >> 2);
            float2 sl = g_sqlab[rg];
            mysq[rid] = sl.x;
            mylab[rid] = __float_as_int(sl.y);
            myrowg[rid] = rg;
        }
    unsigned long long bP[4], bN[4];
#pragma unroll
    for (int r = 0; r < 4; r++) { bP[r] = 0ull; bN[r] = ~0ull; }

    // ---- async load A tile + prefetch B tile 0 + sqlb 0 ----
    for (int i = tid; i < MT * 32; i += 256) {
        int r = i >> 5, c = i & 31;
        cp16(smb + SM_A + (uint32_t)(r * ASTR + c * 16),
             g_Xh + (size_t)(row0 + r) * Dd + 8 * c);
    }
    {
        int cb = colbase;
        for (int i = tid; i < NTILE * 32; i += 256) {
            int r = i >> 5, c = i & 31;
            cp16(smb + SM_B + (uint32_t)(r * ASTR + c * 16),
                 g_Xh + (size_t)(cb + r) * Dd + 8 * c);
        }
        if (tid < NTILE) cp8(smb + SM_SQLB + tid * 8, g_sqlab + cb + tid);
    }
    cp_commit();
    cp_wait0();
    __syncthreads();

#pragma unroll 1
    for (int t = 0; t < NTILES; t++) {
        int buf = t & 1;
        int cb = colbase + t * NTILE;

        // prefetch next tile while computing this one
        if (t + 1 < NTILES) {
            int cb2 = cb + NTILE;
            uint32_t bdst = smb + SM_B + (uint32_t)((buf ^ 1) * BBYTES);
            for (int i = tid; i < NTILE * 32; i += 256) {
                int r = i >> 5, c = i & 31;
                cp16(bdst + (uint32_t)(r * ASTR + c * 16),
                     g_Xh + (size_t)(cb2 + r) * Dd + 8 * c);
            }
            if (tid < NTILE)
                cp8(smb + SM_SQLB + (buf ^ 1) * 1024 + tid * 8, g_sqlab + cb2 + tid);
            cp_commit();
        }

        // ---- GEMM: 128x128x256 via m16n8k16 ----
        float c[2][8][4];
#pragma unroll
        for (int mf = 0; mf < 2; mf++)
#pragma unroll
            for (int nf = 0; nf < 8; nf++)
#pragma unroll
                for (int j = 0; j < 4; j++) c[mf][nf][j] = 0.f;

        uint32_t bbase = smb + SM_B + (uint32_t)(buf * BBYTES) +
                         (uint32_t)(ncol0 + lrow8) * ASTR + lk8b;

#pragma unroll
        for (int ks = 0; ks < 16; ks++) {
            uint32_t a[2][4];
            ldm_x4(a[0][0], a[0][1], a[0][2], a[0][3], a_addr[0] + ks * 32);
            ldm_x4(a[1][0], a[1][1], a[1][2], a[1][3], a_addr[1] + ks * 32);
            uint32_t b[8][2];
#pragma unroll
            for (int p = 0; p < 4; p++) {
                uint32_t r0, r1, r2, r3;
                ldm_x4(r0, r1, r2, r3, bbase + (uint32_t)(p * 16) * ASTR + ks * 32);
                b[2 * p][0] = r0; b[2 * p + 1][0] = r1;
                b[2 * p][1] = r2; b[2 * p + 1][1] = r3;
            }
#pragma unroll
            for (int mf = 0; mf < 2; mf++)
#pragma unroll
                for (int nf = 0; nf < 8; nf++)
                    mma16816(c[mf][nf], a[mf], b[nf]);
        }

        // ---- mining epilogue ----
        float csq[16];
        int clab[16];
        {
            const float2* sq2 = (const float2*)(sm + SM_SQLB + buf * 1024);
#pragma unroll
            for (int nf = 0; nf < 8; nf++)
#pragma unroll
                for (int e = 0; e < 2; e++) {
                    float2 sl = sq2[ncol0 + nf * 8 + 2 * (lane & 3) + e];
                    csq[nf * 2 + e] = sl.x;
                    clab[nf * 2 + e] = __float_as_int(sl.y);
                }
        }
#pragma unroll
        for (int mf = 0; mf < 2; mf++)
#pragma unroll
            for (int nf = 0; nf < 8; nf++)
#pragma unroll
                for (int j = 0; j < 4; j++) {
                    int h = j >> 1, e = j & 1;
                    int rid = mf * 2 + h;
                    int midx = nf * 2 + e;
                    int colg = cb + ncol0 + nf * 8 + 2 * (lane & 3) + e;
                    float d2 = fmaxf(fmaf(-2.f, c[mf][nf][j], mysq[rid] + csq[midx]), 0.f);
                    unsigned int db = __float_as_uint(d2);
                    if (clab[midx] == mylab[rid]) {
                        if (colg != myrowg[rid]) {
                            unsigned long long pk =
                                ((unsigned long long)db << 32) | (unsigned int)(~(unsigned int)colg);
                            if (pk > bP[rid]) bP[rid] = pk;
                        }
                    } else {
                        unsigned long long pk =
                            ((unsigned long long)db << 32) | (unsigned int)colg;
                        if (pk < bN[rid]) bN[rid] = pk;
                    }
                }

        if (t + 1 < NTILES) cp_wait0();
        __syncthreads();
    }

    // ---- merge: quad shfl, then cross-warp via smem, then atomics ----
#pragma unroll
    for (int r = 0; r < 4; r++)
#pragma unroll
        for (int o = 1; o < 4; o <<= 1) {
            unsigned long long p = __shfl_xor_sync(0xffffffffu, bP[r], o);
            if (p > bP[r]) bP[r] = p;
            unsigned long long q = __shfl_xor_sync(0xffffffffu, bN[r], o);
            if (q < bN[r]) bN[r] = q;
        }

    unsigned long long* SP = (unsigned long long*)(sm + SM_A);
    unsigned long long* SN = SP + 128;
    __syncthreads();
    if (warp_n == 1 && (lane & 3) == 0) {
#pragma unroll
        for (int mf = 0; mf < 2; mf++)
#pragma unroll
            for (int h = 0; h < 2; h++) {
                int rl = mrow0 + mf * 16 + h * 8 + (lane >> 2);
                SP[rl] = bP[mf * 2 + h];
                SN[rl] = bN[mf * 2 + h];
            }
    }
    __syncthreads();
    if (warp_n == 0 && (lane & 3) == 0) {
#pragma unroll
        for (int mf = 0; mf < 2; mf++)
#pragma unroll
            for (int h = 0; h < 2; h++) {
                int rid = mf * 2 + h;
                int rl = mrow0 + mf * 16 + h * 8 + (lane >> 2);
                unsigned long long p = SP[rl];
                unsigned long long q = SN[rl];
                if (p > bP[rid]) bP[rid] = p;
                if (q < bN[rid]) bN[rid] = q;
                atomicMax(&g_pos[row0 + rl], bP[rid]);
                atomicMin(&g_neg[row0 + rl], bN[rid]);
            }
    }
}

// ---------------- exact per-anchor recompute (F.pairwise_distance semantics) ----------------
__global__ void loss_kernel(const float* __restrict__ X) {
    int a = blockIdx.x;
    int t = threadIdx.x;  // 64 threads
    unsigned long long p = g_pos[a];
    unsigned long long q = g_neg[a];
    bool valid = (p != 0ull) && (q != ~0ull);
    float lp = 0.f, ln = 0.f;
    if (valid) {
        int pi = (int)(~(unsigned int)(p & 0xFFFFFFFFull));
        int ni = (int)(unsigned int)(q & 0xFFFFFFFFull);
        float4 va = ((const float4*)(X + (size_t)a * Dd))[t];
        float4 vp = ((const float4*)(X + (size_t)pi * Dd))[t];
        float4 vn = ((const float4*)(X + (size_t)ni * Dd))[t];
        float d;
        d = va.x - vp.x + 1e-6f; lp += d * d;
        d = va.y - vp.y + 1e-6f; lp += d * d;
        d = va.z - vp.z + 1e-6f; lp += d * d;
        d = va.w - vp.w + 1e-6f; lp += d * d;
        d = va.x - vn.x + 1e-6f; ln += d * d;
        d = va.y - vn.y + 1e-6f; ln += d * d;
        d = va.z - vn.z + 1e-6f; ln += d * d;
        d = va.w - vn.w + 1e-6f; ln += d * d;
    }
#pragma unroll
    for (int o = 16; o > 0; o >>= 1) {
        lp += __shfl_xor_sync(0xffffffffu, lp, o);
        ln += __shfl_xor_sync(0xffffffffu, ln, o);
    }
    __shared__ float s[4];
    if ((t & 31) == 0) { s[(t >> 5) * 2] = lp; s[(t >> 5) * 2 + 1] = ln; }
    __syncthreads();
    if (t == 0) {
        float pd = sqrtf(s[0] + s[2]);
        float nd = sqrtf(s[1] + s[3]);
        float v = pd - nd + 0.3f;
        g_loss[a] = valid ? (v > 0.f ? v : 0.f) : 0.f;
        g_valid[a] = valid ? 1 : 0;
    }
}

// ---------------- deterministic final reduction ----------------
__global__ void final_kernel(float* __restrict__ out) {
    int t = threadIdx.x;  // 1024
    float s = 0.f;
    int c = 0;
#pragma unroll
    for (int j = 0; j < Bn / 1024; j++) {
        s += g_loss[t + j * 1024];
        c += g_valid[t + j * 1024];
    }
    __shared__ float ss[1024];
    __shared__ int cc[1024];
    ss[t] = s;
    cc[t] = c;
    __syncthreads();
    for (int o = 512; o > 0; o >>= 1) {
        if (t < o) { ss[t] += ss[t + o]; cc[t] += cc[t + o]; }
        __syncthreads();
    }
    if (t == 0) out[0] = ss[0] / (float)(cc[0] > 0 ? cc[0] : 1);
}

extern "C" void kernel_launch(void* const* d_in, const int* in_sizes, int n_in,
                              void* d_out, int out_size) {
    const float* X = (const float*)d_in[0];
    const int* lab32 = (const int*)d_in[1];
    float* out = (float*)d_out;

    cudaFuncSetAttribute(mine_tc, cudaFuncAttributeMaxDynamicSharedMemorySize, SM_TOTAL);

    detect_kernel<<<1, 1>>>(lab32);
    prep_kernel<<<Bn, 64>>>(X, lab32);
    mine_tc<<<dim3(Bn / MT, NSPLIT), 256, SM_TOTAL>>>();
    loss_kernel<<<Bn, 64>>>(X);
    final_kernel<<<1, 1024>>>(out);
}

// round 5
// speedup vs baseline: 6.2833x; 1.2082x over previous
#include <cuda_runtime.h>
#include <cuda_bf16.h>
#include <cstdint>

#define Bn 8192
#define Dd 256
#define MT 128                 // anchors per CTA
#define NTILE 32               // candidates per tile
#define NSPLIT 4
#define CPB (Bn / NSPLIT)      // 2048 cols per CTA
#define NTILES (CPB / NTILE)   // 64

// smem layout (bytes): sqlb 2x32 float2 | A 128x512 | B 2 x 32x512
#define SM_SQLB 0
#define SM_A 1024
#define SM_B (SM_A + 65536)
#define SM_TOTAL (SM_B + 2 * 16384)   // 99328

// ---- scratch (no allocation allowed) ----
__device__ float2 g_sqlab[Bn];
__device__ unsigned long long g_pos[Bn];
__device__ unsigned long long g_neg[Bn];
__device__ float g_loss[Bn];
__device__ int g_valid[Bn];
__device__ int g_l64;
__device__ __nv_bfloat16 g_Xh[(size_t)Bn * Dd];   // 4MB bf16 copy

// ---------------- helpers ----------------
__device__ __forceinline__ uint32_t smem_u32(const void* p) {
    uint32_t a;
    asm("{ .reg .u64 t; cvta.to.shared.u64 t, %1; cvt.u32.u64 %0, t; }" : "=r"(a) : "l"(p));
    return a;
}
__device__ __forceinline__ void ldm_x4(uint32_t& r0, uint32_t& r1, uint32_t& r2, uint32_t& r3,
                                       uint32_t addr) {
    asm volatile("ldmatrix.sync.aligned.m8n8.x4.shared.b16 {%0,%1,%2,%3}, [%4];"
                 : "=r"(r0), "=r"(r1), "=r"(r2), "=r"(r3) : "r"(addr));
}
__device__ __forceinline__ void mma16816(float* c, const uint32_t* a, const uint32_t* b) {
    asm volatile(
        "mma.sync.aligned.m16n8k16.row.col.f32.bf16.bf16.f32 "
        "{%0,%1,%2,%3}, {%4,%5,%6,%7}, {%8,%9}, {%0,%1,%2,%3};"
        : "+f"(c[0]), "+f"(c[1]), "+f"(c[2]), "+f"(c[3])
        : "r"(a[0]), "r"(a[1]), "r"(a[2]), "r"(a[3]), "r"(b[0]), "r"(b[1]));
}
__device__ __forceinline__ void cp16(uint32_t dst, const void* src) {
    asm volatile("cp.async.cg.shared.global [%0], [%1], 16;" :: "r"(dst), "l"(src) : "memory");
}
__device__ __forceinline__ void cp8(uint32_t dst, const void* src) {
    asm volatile("cp.async.ca.shared.global [%0], [%1], 8;" :: "r"(dst), "l"(src) : "memory");
}
__device__ __forceinline__ void cp_commit() { asm volatile("cp.async.commit_group;" ::: "memory"); }
__device__ __forceinline__ void cp_wait0() { asm volatile("cp.async.wait_group 0;" ::: "memory"); }

// XOR swizzle: 512B logical rows, 16B chunks c in [0,32); permute low 3 bits by row
__device__ __forceinline__ uint32_t swz(int r, int c) {
    return (uint32_t)(r * 512 + ((((c & 24) | ((c ^ r) & 7))) << 4));
}

// ---------------- label dtype layout probe ----------------
__global__ void detect_kernel(const int* __restrict__ lab32) {
    int any = 0;
    for (int i = 1; i < 256; i += 2) any |= lab32[i];
    g_l64 = (any == 0) ? 1 : 0;
}

// ---------------- prep: warp per row ----------------
__global__ void prep_kernel(const float* __restrict__ X, const int* __restrict__ lab32) {
    int row = blockIdx.x * 8 + (threadIdx.x >> 5);
    int lane = threadIdx.x & 31;
    const float4* x4 = (const float4*)(X + (size_t)row * Dd);
    float4 v0 = x4[2 * lane];
    float4 v1 = x4[2 * lane + 1];
    // pack 8 bf16 = 16B
    __nv_bfloat162 b0 = __nv_bfloat162(__float2bfloat16(v0.x), __float2bfloat16(v0.y));
    __nv_bfloat162 b1 = __nv_bfloat162(__float2bfloat16(v0.z), __float2bfloat16(v0.w));
    __nv_bfloat162 b2 = __nv_bfloat162(__float2bfloat16(v1.x), __float2bfloat16(v1.y));
    __nv_bfloat162 b3 = __nv_bfloat162(__float2bfloat16(v1.z), __float2bfloat16(v1.w));
    uint4 pk;
    pk.x = *(uint32_t*)&b0; pk.y = *(uint32_t*)&b1;
    pk.z = *(uint32_t*)&b2; pk.w = *(uint32_t*)&b3;
    *(uint4*)(g_Xh + (size_t)row * Dd + 8 * lane) = pk;

    float s = v0.x * v0.x + v0.y * v0.y + v0.z * v0.z + v0.w * v0.w
            + v1.x * v1.x + v1.y * v1.y + v1.z * v1.z + v1.w * v1.w;
#pragma unroll
    for (int o = 16; o > 0; o >>= 1) s += __shfl_xor_sync(0xffffffffu, s, o);
    if (lane == 0) {
        float2 sl;
        sl.x = s;
        sl.y = __int_as_float(g_l64 ? lab32[2 * row] : lab32[row]);
        g_sqlab[row] = sl;
        g_pos[row] = 0ull;
        g_neg[row] = ~0ull;
    }
}

// ---------------- HMMA fused GEMM + hard mining (A-stationary, 2 CTAs/SM) ----------------
__global__ void __launch_bounds__(256, 2) mine_tc(void) {
    extern __shared__ char sm[];
    uint32_t smb = smem_u32(sm);
    int tid = threadIdx.x;
    int wid = tid >> 5;        // warp owns rows wid*16 .. wid*16+15
    int lane = tid & 31;

    int row0 = blockIdx.x * MT;
    int colbase = blockIdx.y * CPB;

    // ---- async load A tile + B tile 0 + sqlb 0 ----
    for (int i = tid; i < MT * 32; i += 256) {
        int r = i >> 5, c = i & 31;
        cp16(smb + SM_A + swz(r, c), g_Xh + (size_t)(row0 + r) * Dd + 8 * c);
    }
    for (int i = tid; i < NTILE * 32; i += 256) {
        int r = i >> 5, c = i & 31;
        cp16(smb + SM_B + swz(r, c), g_Xh + (size_t)(colbase + r) * Dd + 8 * c);
    }
    if (tid < NTILE) cp8(smb + SM_SQLB + tid * 8, g_sqlab + colbase + tid);
    cp_commit();

    // row metadata (2 rows per thread: h=0,1)
    float mysq[2];
    int mylab[2], myrowg[2];
#pragma unroll
    for (int h = 0; h < 2; h++) {
        int rg = row0 + wid * 16 + h * 8 + (lane >> 2);
        float2 sl = g_sqlab[rg];
        mysq[h] = sl.x;
        mylab[h] = __float_as_int(sl.y);
        myrowg[h] = rg;
    }
    unsigned long long bP[2] = {0ull, 0ull};
    unsigned long long bN[2] = {~0ull, ~0ull};

    cp_wait0();
    __syncthreads();

    // ---- hoist A fragments into registers (tile-invariant) ----
    uint32_t a[16][4];
    {
        int arow = wid * 16 + (lane & 15);
        int khalf = lane >> 4;
#pragma unroll
        for (int ks = 0; ks < 16; ks++)
            ldm_x4(a[ks][0], a[ks][1], a[ks][2], a[ks][3],
                   smb + SM_A + swz(arow, 2 * ks + khalf));
    }

    int brow01 = lane & 15;          // cols 0-15 of tile
    int bkh = lane >> 4;

#pragma unroll 1
    for (int t = 0; t < NTILES; t++) {
        int buf = t & 1;
        int cb = colbase + t * NTILE;

        // prefetch next tile
        if (t + 1 < NTILES) {
            int cb2 = cb + NTILE;
            uint32_t bdst = smb + SM_B + (uint32_t)((buf ^ 1) * 16384);
            for (int i = tid; i < NTILE * 32; i += 256) {
                int r = i >> 5, c = i & 31;
                cp16(bdst + swz(r, c), g_Xh + (size_t)(cb2 + r) * Dd + 8 * c);
            }
            if (tid < NTILE)
                cp8(smb + SM_SQLB + (buf ^ 1) * 256 + tid * 8, g_sqlab + cb2 + tid);
            cp_commit();
        }

        // ---- GEMM 128x32x256: per warp 16x32, 4 HMMA per kstep ----
        float acc[4][4];
#pragma unroll
        for (int nf = 0; nf < 4; nf++)
#pragma unroll
            for (int j = 0; j < 4; j++) acc[nf][j] = 0.f;

        uint32_t bbuf = smb + SM_B + (uint32_t)(buf * 16384);
#pragma unroll
        for (int ks = 0; ks < 16; ks++) {
            int chunk = 2 * ks + bkh;
            uint32_t b[4][2];
            {
                uint32_t r0, r1, r2, r3;
                ldm_x4(r0, r1, r2, r3, bbuf + swz(brow01, chunk));
                b[0][0] = r0; b[1][0] = r1; b[0][1] = r2; b[1][1] = r3;
                ldm_x4(r0, r1, r2, r3, bbuf + swz(16 + brow01, chunk));
                b[2][0] = r0; b[3][0] = r1; b[2][1] = r2; b[3][1] = r3;
            }
#pragma unroll
            for (int nf = 0; nf < 4; nf++)
                mma16816(acc[nf], a[ks], b[nf]);
        }

        // ---- mining epilogue: 16 elements/thread ----
        const float2* sq2 = (const float2*)(sm + SM_SQLB + buf * 256);
#pragma unroll
        for (int nf = 0; nf < 4; nf++)
#pragma unroll
            for (int e = 0; e < 2; e++) {
                int cl = nf * 8 + 2 * (lane & 3) + e;
                float2 sl = sq2[cl];
                int colg = cb + cl;
                int clab = __float_as_int(sl.y);
#pragma unroll
                for (int h = 0; h < 2; h++) {
                    float d2 = fmaxf(fmaf(-2.f, acc[nf][h * 2 + e], mysq[h] + sl.x), 0.f);
                    unsigned int db = __float_as_uint(d2);
                    if (clab == mylab[h]) {
                        if (colg != myrowg[h]) {
                            unsigned long long pk =
                                ((unsigned long long)db << 32) | (unsigned int)(~(unsigned int)colg);
                            if (pk > bP[h]) bP[h] = pk;
                        }
                    } else {
                        unsigned long long pk =
                            ((unsigned long long)db << 32) | (unsigned int)colg;
                        if (pk < bN[h]) bN[h] = pk;
                    }
                }
            }

        if (t + 1 < NTILES) cp_wait0();
        __syncthreads();
    }

    // ---- merge quad (lanes sharing a row), then atomics (rows unique per warp) ----
#pragma unroll
    for (int h = 0; h < 2; h++) {
#pragma unroll
        for (int o = 1; o < 4; o <<= 1) {
            unsigned long long p = __shfl_xor_sync(0xffffffffu, bP[h], o);
            if (p > bP[h]) bP[h] = p;
            unsigned long long q = __shfl_xor_sync(0xffffffffu, bN[h], o);
            if (q < bN[h]) bN[h] = q;
        }
        if ((lane & 3) == 0) {
            atomicMax(&g_pos[myrowg[h]], bP[h]);
            atomicMin(&g_neg[myrowg[h]], bN[h]);
        }
    }
}

// ---------------- exact per-anchor recompute: warp per anchor ----------------
__global__ void loss_kernel(const float* __restrict__ X) {
    int a = blockIdx.x * 8 + (threadIdx.x >> 5);
    int lane = threadIdx.x & 31;
    unsigned long long p = g_pos[a];
    unsigned long long q = g_neg[a];
    bool valid = (p != 0ull) && (q != ~0ull);
    float lp = 0.f, ln = 0.f;
    if (valid) {
        int pi = (int)(~(unsigned int)(p & 0xFFFFFFFFull));
        int ni = (int)(unsigned int)(q & 0xFFFFFFFFull);
        const float4* va = (const float4*)(X + (size_t)a * Dd);
        const float4* vp = (const float4*)(X + (size_t)pi * Dd);
        const float4* vn = (const float4*)(X + (size_t)ni * Dd);
#pragma unroll
        for (int u = 0; u < 2; u++) {
            float4 x = va[2 * lane + u];
            float4 y = vp[2 * lane + u];
            float4 z = vn[2 * lane + u];
            float d;
            d = x.x - y.x + 1e-6f; lp += d * d;
            d = x.y - y.y + 1e-6f; lp += d * d;
            d = x.z - y.z + 1e-6f; lp += d * d;
            d = x.w - y.w + 1e-6f; lp += d * d;
            d = x.x - z.x + 1e-6f; ln += d * d;
            d = x.y - z.y + 1e-6f; ln += d * d;
            d = x.z - z.z + 1e-6f; ln += d * d;
            d = x.w - z.w + 1e-6f; ln += d * d;
        }
    }
#pragma unroll
    for (int o = 16; o > 0; o >>= 1) {
        lp += __shfl_xor_sync(0xffffffffu, lp, o);
        ln += __shfl_xor_sync(0xffffffffu, ln, o);
    }
    if (lane == 0) {
        float v = sqrtf(lp) - sqrtf(ln) + 0.3f;
        g_loss[a] = valid ? (v > 0.f ? v : 0.f) : 0.f;
        g_valid[a] = valid ? 1 : 0;
    }
}

// ---------------- deterministic final reduction ----------------
__global__ void final_kernel(float* __restrict__ out) {
    int t = threadIdx.x;  // 1024
    float s = 0.f;
    int c = 0;
#pragma unroll
    for (int j = 0; j < Bn / 1024; j++) {
        s += g_loss[t + j * 1024];
        c += g_valid[t + j * 1024];
    }
    __shared__ float ss[1024];
    __shared__ int cc[1024];
    ss[t] = s;
    cc[t] = c;
    __syncthreads();
    for (int o = 512; o > 0; o >>= 1) {
        if (t < o) { ss[t] += ss[t + o]; cc[t] += cc[t + o]; }
        __syncthreads();
    }
    if (t == 0) out[0] = ss[0] / (float)(cc[0] > 0 ? cc[0] : 1);
}

extern "C" void kernel_launch(void* const* d_in, const int* in_sizes, int n_in,
                              void* d_out, int out_size) {
    const float* X = (const float*)d_in[0];
    const int* lab32 = (const int*)d_in[1];
    float* out = (float*)d_out;

    cudaFuncSetAttribute(mine_tc, cudaFuncAttributeMaxDynamicSharedMemorySize, SM_TOTAL);

    detect_kernel<<<1, 1>>>(lab32);
    prep_kernel<<<Bn / 8, 256>>>(X, lab32);
    mine_tc<<<dim3(Bn / MT, NSPLIT), 256, SM_TOTAL>>>();
    loss_kernel<<<Bn / 8, 256>>>(X);
    final_kernel<<<1, 1024>>>(out);
}

// round 6
// speedup vs baseline: 6.6228x; 1.0540x over previous
#include <cuda_runtime.h>
#include <cuda_bf16.h>
#include <cstdint>

#define Bn 8192
#define Dd 256
#define MT 128                 // anchors per CTA
#define NTILE 32               // candidates per tile
#define NSPLIT 4
#define NTILES 33              // forward half-circle: 4 splits x 33 x 32 = 4224 cols
#define CWIDTH (NTILES * NTILE)  // 1056 cols per CTA

// smem layout (bytes): sqlb 2x32 float2 | A 128x512 | B 2 x 32x512
#define SM_SQLB 0
#define SM_A 1024
#define SM_B (SM_A + 65536)
#define SM_TOTAL (SM_B + 2 * 16384)   // 99328

// ---- scratch (no allocation allowed) ----
__device__ float2 g_sqlab[Bn];
__device__ unsigned long long g_pos[Bn];
__device__ unsigned long long g_neg[Bn];
__device__ float g_loss[Bn];
__device__ int g_valid[Bn];
__device__ int g_l64;
__device__ __nv_bfloat16 g_Xh[(size_t)Bn * Dd];   // 4MB bf16 copy

// ---------------- helpers ----------------
__device__ __forceinline__ uint32_t smem_u32(const void* p) {
    uint32_t a;
    asm("{ .reg .u64 t; cvta.to.shared.u64 t, %1; cvt.u32.u64 %0, t; }" : "=r"(a) : "l"(p));
    return a;
}
__device__ __forceinline__ void ldm_x4(uint32_t& r0, uint32_t& r1, uint32_t& r2, uint32_t& r3,
                                       uint32_t addr) {
    asm volatile("ldmatrix.sync.aligned.m8n8.x4.shared.b16 {%0,%1,%2,%3}, [%4];"
                 : "=r"(r0), "=r"(r1), "=r"(r2), "=r"(r3) : "r"(addr));
}
__device__ __forceinline__ void mma16816(float* c, const uint32_t* a, const uint32_t* b) {
    asm volatile(
        "mma.sync.aligned.m16n8k16.row.col.f32.bf16.bf16.f32 "
        "{%0,%1,%2,%3}, {%4,%5,%6,%7}, {%8,%9}, {%0,%1,%2,%3};"
        : "+f"(c[0]), "+f"(c[1]), "+f"(c[2]), "+f"(c[3])
        : "r"(a[0]), "r"(a[1]), "r"(a[2]), "r"(a[3]), "r"(b[0]), "r"(b[1]));
}
__device__ __forceinline__ void cp16(uint32_t dst, const void* src) {
    asm volatile("cp.async.cg.shared.global [%0], [%1], 16;" :: "r"(dst), "l"(src) : "memory");
}
__device__ __forceinline__ void cp8(uint32_t dst, const void* src) {
    asm volatile("cp.async.ca.shared.global [%0], [%1], 8;" :: "r"(dst), "l"(src) : "memory");
}
__device__ __forceinline__ void cp_commit() { asm volatile("cp.async.commit_group;" ::: "memory"); }
__device__ __forceinline__ void cp_wait0() { asm volatile("cp.async.wait_group 0;" ::: "memory"); }

// XOR swizzle: 512B logical rows, 16B chunks c in [0,32); permute low 3 bits by row
__device__ __forceinline__ uint32_t swz(int r, int c) {
    return (uint32_t)(r * 512 + ((((c & 24) | ((c ^ r) & 7))) << 4));
}

// ---------------- label dtype layout probe ----------------
__global__ void detect_kernel(const int* __restrict__ lab32) {
    int any = 0;
    for (int i = 1; i < 256; i += 2) any |= lab32[i];
    g_l64 = (any == 0) ? 1 : 0;
}

// ---------------- prep: warp per row ----------------
__global__ void prep_kernel(const float* __restrict__ X, const int* __restrict__ lab32) {
    int row = blockIdx.x * 8 + (threadIdx.x >> 5);
    int lane = threadIdx.x & 31;
    const float4* x4 = (const float4*)(X + (size_t)row * Dd);
    float4 v0 = x4[2 * lane];
    float4 v1 = x4[2 * lane + 1];
    __nv_bfloat162 b0 = __nv_bfloat162(__float2bfloat16(v0.x), __float2bfloat16(v0.y));
    __nv_bfloat162 b1 = __nv_bfloat162(__float2bfloat16(v0.z), __float2bfloat16(v0.w));
    __nv_bfloat162 b2 = __nv_bfloat162(__float2bfloat16(v1.x), __float2bfloat16(v1.y));
    __nv_bfloat162 b3 = __nv_bfloat162(__float2bfloat16(v1.z), __float2bfloat16(v1.w));
    uint4 pk;
    pk.x = *(uint32_t*)&b0; pk.y = *(uint32_t*)&b1;
    pk.z = *(uint32_t*)&b2; pk.w = *(uint32_t*)&b3;
    *(uint4*)(g_Xh + (size_t)row * Dd + 8 * lane) = pk;

    float s = v0.x * v0.x + v0.y * v0.y + v0.z * v0.z + v0.w * v0.w
            + v1.x * v1.x + v1.y * v1.y + v1.z * v1.z + v1.w * v1.w;
#pragma unroll
    for (int o = 16; o > 0; o >>= 1) s += __shfl_xor_sync(0xffffffffu, s, o);
    if (lane == 0) {
        float2 sl;
        sl.x = s;
        sl.y = __int_as_float(g_l64 ? lab32[2 * row] : lab32[row]);
        g_sqlab[row] = sl;
        g_pos[row] = 0ull;
        g_neg[row] = ~0ull;
    }
}

// ---------------- HMMA fused GEMM + symmetric hard mining ----------------
__global__ void __launch_bounds__(256, 2) mine_tc(void) {
    extern __shared__ char sm[];
    uint32_t smb = smem_u32(sm);
    int tid = threadIdx.x;
    int wid = tid >> 5;        // warp owns rows wid*16 .. wid*16+15
    int lane = tid & 31;

    int row0 = blockIdx.x * MT;
    int cb0 = row0 + blockIdx.y * CWIDTH;   // forward column window start

    // ---- async load A tile + B tile 0 + sqlb 0 ----
    for (int i = tid; i < MT * 32; i += 256) {
        int r = i >> 5, c = i & 31;
        cp16(smb + SM_A + swz(r, c), g_Xh + (size_t)(row0 + r) * Dd + 8 * c);
    }
    {
        int cb = cb0 & (Bn - 1);
        for (int i = tid; i < NTILE * 32; i += 256) {
            int r = i >> 5, c = i & 31;
            cp16(smb + SM_B + swz(r, c), g_Xh + (size_t)(cb + r) * Dd + 8 * c);
        }
        if (tid < NTILE) cp8(smb + SM_SQLB + tid * 8, g_sqlab + cb + tid);
    }
    cp_commit();

    // row metadata (2 rows per thread: h=0,1)
    float mysq[2];
    int mylab[2], myrowg[2];
#pragma unroll
    for (int h = 0; h < 2; h++) {
        int rg = row0 + wid * 16 + h * 8 + (lane >> 2);
        float2 sl = g_sqlab[rg];
        mysq[h] = sl.x;
        mylab[h] = __float_as_int(sl.y);
        myrowg[h] = rg;
    }
    unsigned long long bP[2] = {0ull, 0ull};
    unsigned long long bN[2] = {~0ull, ~0ull};

    cp_wait0();
    __syncthreads();

    // ---- hoist A fragments into registers (tile-invariant) ----
    uint32_t a[16][4];
    {
        int arow = wid * 16 + (lane & 15);
        int khalf = lane >> 4;
#pragma unroll
        for (int ks = 0; ks < 16; ks++)
            ldm_x4(a[ks][0], a[ks][1], a[ks][2], a[ks][3],
                   smb + SM_A + swz(arow, 2 * ks + khalf));
    }

    int brow01 = lane & 15;
    int bkh = lane >> 4;

#pragma unroll 1
    for (int t = 0; t < NTILES; t++) {
        int buf = t & 1;
        int cb = (cb0 + t * NTILE) & (Bn - 1);

        // prefetch next tile
        if (t + 1 < NTILES) {
            int cb2 = (cb0 + (t + 1) * NTILE) & (Bn - 1);
            uint32_t bdst = smb + SM_B + (uint32_t)((buf ^ 1) * 16384);
            for (int i = tid; i < NTILE * 32; i += 256) {
                int r = i >> 5, c = i & 31;
                cp16(bdst + swz(r, c), g_Xh + (size_t)(cb2 + r) * Dd + 8 * c);
            }
            if (tid < NTILE)
                cp8(smb + SM_SQLB + (buf ^ 1) * 256 + tid * 8, g_sqlab + cb2 + tid);
            cp_commit();
        }

        // ---- GEMM 128x32x256: per warp 16x32, 4 HMMA per kstep ----
        float acc[4][4];
#pragma unroll
        for (int nf = 0; nf < 4; nf++)
#pragma unroll
            for (int j = 0; j < 4; j++) acc[nf][j] = 0.f;

        uint32_t bbuf = smb + SM_B + (uint32_t)(buf * 16384);
#pragma unroll
        for (int ks = 0; ks < 16; ks++) {
            int chunk = 2 * ks + bkh;
            uint32_t b[4][2];
            {
                uint32_t r0, r1, r2, r3;
                ldm_x4(r0, r1, r2, r3, bbuf + swz(brow01, chunk));
                b[0][0] = r0; b[1][0] = r1; b[0][1] = r2; b[1][1] = r3;
                ldm_x4(r0, r1, r2, r3, bbuf + swz(16 + brow01, chunk));
                b[2][0] = r0; b[3][0] = r1; b[2][1] = r2; b[3][1] = r3;
            }
#pragma unroll
            for (int nf = 0; nf < 4; nf++)
                mma16816(acc[nf], a[ks], b[nf]);
        }

        // ---- two-sided mining epilogue ----
        const float2* sq2 = (const float2*)(sm + SM_SQLB + buf * 256);
#pragma unroll
        for (int nf = 0; nf < 4; nf++)
#pragma unroll
            for (int e = 0; e < 2; e++) {
                int cl = nf * 8 + 2 * (lane & 3) + e;
                float2 sl = sq2[cl];
                int colg = cb + cl;
                int clab = __float_as_int(sl.y);
                unsigned long long cp = 0ull, cn = ~0ull;
#pragma unroll
                for (int h = 0; h < 2; h++) {
                    float d2 = fmaxf(fmaf(-2.f, acc[nf][h * 2 + e], mysq[h] + sl.x), 0.f);
                    unsigned int db = __float_as_uint(d2);
                    if (clab == mylab[h]) {
                        if (colg != myrowg[h]) {
                            // row-side: anchor = row, candidate = col
                            unsigned long long pk =
                                ((unsigned long long)db << 32) | (unsigned int)(~(unsigned int)colg);
                            if (pk > bP[h]) bP[h] = pk;
                            // col-side: anchor = col, candidate = row
                            unsigned long long ck =
                                ((unsigned long long)db << 32) | (unsigned int)(~(unsigned int)myrowg[h]);
                            if (ck > cp) cp = ck;
                        }
                    } else {
                        unsigned long long pk =
                            ((unsigned long long)db << 32) | (unsigned int)colg;
                        if (pk < bN[h]) bN[h] = pk;
                        unsigned long long ck =
                            ((unsigned long long)db << 32) | (unsigned int)myrowg[h];
                        if (ck < cn) cn = ck;
                    }
                }
                // reduce col-side over the warp's 16 rows (lane strides 4,8,16)
#pragma unroll
                for (int s = 4; s <= 16; s <<= 1) {
                    unsigned long long p = __shfl_xor_sync(0xffffffffu, cp, s);
                    if (p > cp) cp = p;
                    unsigned long long q = __shfl_xor_sync(0xffffffffu, cn, s);
                    if (q < cn) cn = q;
                }
                if (lane < 4) {
                    if (cp) atomicMax(&g_pos[colg], cp);
                    if (cn != ~0ull) atomicMin(&g_neg[colg], cn);
                }
            }

        if (t + 1 < NTILES) cp_wait0();
        __syncthreads();
    }

    // ---- row-side merge: quad shfl, then atomics (rows unique per warp) ----
#pragma unroll
    for (int h = 0; h < 2; h++) {
#pragma unroll
        for (int o = 1; o < 4; o <<= 1) {
            unsigned long long p = __shfl_xor_sync(0xffffffffu, bP[h], o);
            if (p > bP[h]) bP[h] = p;
            unsigned long long q = __shfl_xor_sync(0xffffffffu, bN[h], o);
            if (q < bN[h]) bN[h] = q;
        }
        if ((lane & 3) == 0) {
            atomicMax(&g_pos[myrowg[h]], bP[h]);
            atomicMin(&g_neg[myrowg[h]], bN[h]);
        }
    }
}

// ---------------- exact per-anchor recompute: warp per anchor ----------------
__global__ void loss_kernel(const float* __restrict__ X) {
    int a = blockIdx.x * 8 + (threadIdx.x >> 5);
    int lane = threadIdx.x & 31;
    unsigned long long p = g_pos[a];
    unsigned long long q = g_neg[a];
    bool valid = (p != 0ull) && (q != ~0ull);
    float lp = 0.f, ln = 0.f;
    if (valid) {
        int pi = (int)(~(unsigned int)(p & 0xFFFFFFFFull));
        int ni = (int)(unsigned int)(q & 0xFFFFFFFFull);
        const float4* va = (const float4*)(X + (size_t)a * Dd);
        const float4* vp = (const float4*)(X + (size_t)pi * Dd);
        const float4* vn = (const float4*)(X + (size_t)ni * Dd);
#pragma unroll
        for (int u = 0; u < 2; u++) {
            float4 x = va[2 * lane + u];
            float4 y = vp[2 * lane + u];
            float4 z = vn[2 * lane + u];
            float d;
            d = x.x - y.x + 1e-6f; lp += d * d;
            d = x.y - y.y + 1e-6f; lp += d * d;
            d = x.z - y.z + 1e-6f; lp += d * d;
            d = x.w - y.w + 1e-6f; lp += d * d;
            d = x.x - z.x + 1e-6f; ln += d * d;
            d = x.y - z.y + 1e-6f; ln += d * d;
            d = x.z - z.z + 1e-6f; ln += d * d;
            d = x.w - z.w + 1e-6f; ln += d * d;
        }
    }
#pragma unroll
    for (int o = 16; o > 0; o >>= 1) {
        lp += __shfl_xor_sync(0xffffffffu, lp, o);
        ln += __shfl_xor_sync(0xffffffffu, ln, o);
    }
    if (lane == 0) {
        float v = sqrtf(lp) - sqrtf(ln) + 0.3f;
        g_loss[a] = valid ? (v > 0.f ? v : 0.f) : 0.f;
        g_valid[a] = valid ? 1 : 0;
    }
}

// ---------------- deterministic final reduction ----------------
__global__ void final_kernel(float* __restrict__ out) {
    int t = threadIdx.x;  // 1024
    float s = 0.f;
    int c = 0;
#pragma unroll
    for (int j = 0; j < Bn / 1024; j++) {
        s += g_loss[t + j * 1024];
        c += g_valid[t + j * 1024];
    }
    __shared__ float ss[1024];
    __shared__ int cc[1024];
    ss[t] = s;
    cc[t] = c;
    __syncthreads();
    for (int o = 512; o > 0; o >>= 1) {
        if (t < o) { ss[t] += ss[t + o]; cc[t] += cc[t + o]; }
        __syncthreads();
    }
    if (t == 0) out[0] = ss[0] / (float)(cc[0] > 0 ? cc[0] : 1);
}

extern "C" void kernel_launch(void* const* d_in, const int* in_sizes, int n_in,
                              void* d_out, int out_size) {
    const float* X = (const float*)d_in[0];
    const int* lab32 = (const int*)d_in[1];
    float* out = (float*)d_out;

    cudaFuncSetAttribute(mine_tc, cudaFuncAttributeMaxDynamicSharedMemorySize, SM_TOTAL);

    detect_kernel<<<1, 1>>>(lab32);
    prep_kernel<<<Bn / 8, 256>>>(X, lab32);
    mine_tc<<<dim3(Bn / MT, NSPLIT), 256, SM_TOTAL>>>();
    loss_kernel<<<Bn / 8, 256>>>(X);
    final_kernel<<<1, 1024>>>(out);
}